// round 16
// baseline (speedup 1.0000x reference)
#include <cuda_runtime.h>
#include <cstdint>
#include <cfloat>

// Problem constants (fixed by dataset)
#define BB 64
#define TT 128
#define SS 512
#define EE 1024
#define DD 512
#define NEGINF (-1.0e10f)
#define PAD 132

// b16 tile geometry: [128 rows][16 k] b16, 48B row pitch (32B data + 16B pad)
#define BPITCH 48
#define BTILE  (128 * BPITCH)      // 6144 B
#define BSTG   (4 * BTILE)         // Ah, Al, Bh, Bl per stage = 24576 B
#define SMEM_BF (2 * BSTG)         // 49152 B

// Scratch (allocation-free rule: device globals)
__device__ uint32_t g_Ph[(size_t)BB * TT * EE / 2];  // P hi (bf16x2)
__device__ uint32_t g_Pl[(size_t)BB * TT * EE / 2];  // P lo (bf16x2)
__device__ float g_wc[(size_t)BB * TT * EE];
__device__ float g_c[(size_t)BB * TT];
__device__ float g_attn_c[(size_t)BB * TT * SS];     // compacted attn (zero tail)
__device__ float g_ep[2 * (size_t)BB * TT * SS];     // split-K partials (energy, then out)
__device__ int   g_idx[(size_t)BB * SS];
__device__ int   g_cnt[BB];
__device__ float g_attn_scratch[(size_t)BB * TT * SS];
__device__ float g_me_scratch[(size_t)BB * TT * SS];

// ---------------------------------------------------------------------------
// helpers
// ---------------------------------------------------------------------------
__device__ __forceinline__ uint32_t smem_u32(const void* p) {
    uint32_t a;
    asm("{ .reg .u64 t; cvta.to.shared.u64 t, %1; cvt.u32.u64 %0, t; }"
        : "=r"(a) : "l"(p));
    return a;
}

#define LDSM4(d0, d1, d2, d3, a)                                              \
    asm volatile("ldmatrix.sync.aligned.m8n8.x4.shared.b16 {%0,%1,%2,%3}, [%4];" \
                 : "=r"(d0), "=r"(d1), "=r"(d2), "=r"(d3) : "r"(a))

__device__ __forceinline__ void mma16(float* d, const uint32_t* a, const uint32_t* b) {
    asm volatile(
        "mma.sync.aligned.m16n8k16.row.col.f32.bf16.bf16.f32 "
        "{%0,%1,%2,%3}, {%4,%5,%6,%7}, {%8,%9}, {%0,%1,%2,%3};"
        : "+f"(d[0]), "+f"(d[1]), "+f"(d[2]), "+f"(d[3])
        : "r"(a[0]), "r"(a[1]), "r"(a[2]), "r"(a[3]), "r"(b[0]), "r"(b[1]));
}

__device__ __forceinline__ void mma16h(float* d, const uint32_t* a, const uint32_t* b) {
    asm volatile(
        "mma.sync.aligned.m16n8k16.row.col.f32.f16.f16.f32 "
        "{%0,%1,%2,%3}, {%4,%5,%6,%7}, {%8,%9}, {%0,%1,%2,%3};"
        : "+f"(d[0]), "+f"(d[1]), "+f"(d[2]), "+f"(d[3])
        : "r"(a[0]), "r"(a[1]), "r"(a[2]), "r"(a[3]), "r"(b[0]), "r"(b[1]));
}

// pack two fp32 into bf16x2 hi + residual lo
__device__ __forceinline__ void split2(float x, float y, uint32_t& h, uint32_t& l) {
    asm("cvt.rn.satfinite.bf16x2.f32 %0, %1, %2;" : "=r"(h) : "f"(y), "f"(x));
    const float hx = __uint_as_float(h << 16);
    const float hy = __uint_as_float(h & 0xFFFF0000u);
    asm("cvt.rn.satfinite.bf16x2.f32 %0, %1, %2;" : "=r"(l) : "f"(y - hy), "f"(x - hx));
}

// ---------------------------------------------------------------------------
// bf16 split staging
// ---------------------------------------------------------------------------
#define STAGE_BF2(hi, lo, v, p) do {                                          \
    const int _r = lrow + (p) * 64;                                           \
    uint32_t _h0, _h1, _l0, _l1;                                              \
    split2((v).x, (v).y, _h0, _l0);                                           \
    split2((v).z, (v).w, _h1, _l1);                                           \
    *(uint2*)((hi) + _r * BPITCH + (tid & 3) * 8) = make_uint2(_h0, _h1);     \
    *(uint2*)((lo) + _r * BPITCH + (tid & 3) * 8) = make_uint2(_l0, _l1);     \
} while (0)

// pre-split staging: data already bf16 hi/lo pairs in gmem
#define STAGE_PRE(hi, lo, hv, lv, p) do {                                     \
    const int _r = lrow + (p) * 64;                                           \
    *(uint2*)((hi) + _r * BPITCH + (tid & 3) * 8) = (hv);                     \
    *(uint2*)((lo) + _r * BPITCH + (tid & 3) * 8) = (lv);                     \
} while (0)

#define COMPUTE_BF_LDSM(AHB, ALB, BHB, BLB) do {                              \
    uint32_t ah[4][4], al[4][4], bh[4][2], bl[4][2];                          \
    _Pragma("unroll")                                                         \
    for (int mi = 0; mi < 4; mi++) {                                          \
        const uint32_t _ao = aoff + mi * (16 * BPITCH);                       \
        LDSM4(ah[mi][0], ah[mi][1], ah[mi][2], ah[mi][3], (AHB) + _ao);       \
        LDSM4(al[mi][0], al[mi][1], al[mi][2], al[mi][3], (ALB) + _ao);       \
    }                                                                         \
    _Pragma("unroll")                                                         \
    for (int p = 0; p < 2; p++) {                                             \
        const uint32_t _bo = boff + p * (16 * BPITCH);                        \
        LDSM4(bh[2*p][0], bh[2*p][1], bh[2*p+1][0], bh[2*p+1][1], (BHB) + _bo); \
        LDSM4(bl[2*p][0], bl[2*p][1], bl[2*p+1][0], bl[2*p+1][1], (BLB) + _bo); \
    }                                                                         \
    _Pragma("unroll")                                                         \
    for (int mi = 0; mi < 4; mi++)                                            \
        _Pragma("unroll")                                                     \
        for (int nj = 0; nj < 4; nj++) {                                      \
            mma16(acc[mi][nj], ah[mi], bh[nj]);                               \
            mma16(acc[mi][nj], ah[mi], bl[nj]);                               \
            mma16(acc[mi][nj], al[mi], bh[nj]);                               \
        }                                                                     \
} while (0)

// ---------------------------------------------------------------------------
// fp16 staging/compute (k_wc / k_out)
// ---------------------------------------------------------------------------
#define STAGE_F16(dst, v, p) do {                                             \
    const int _r = lrow + (p) * 64;                                           \
    uint32_t _h0, _h1;                                                        \
    asm("cvt.rn.f16x2.f32 %0, %1, %2;" : "=r"(_h0) : "f"((v).y), "f"((v).x)); \
    asm("cvt.rn.f16x2.f32 %0, %1, %2;" : "=r"(_h1) : "f"((v).w), "f"((v).z)); \
    *(uint2*)((dst) + _r * BPITCH + (tid & 3) * 8) = make_uint2(_h0, _h1);    \
} while (0)

#define STAGE_RAW(H, v, p) *(float4*)&H[krow + (p) * 8][ncol] = (v)

#define COMPUTE_F16(A16B, BP) do {                                            \
    uint32_t af[4][4], bfr[4][2];                                             \
    _Pragma("unroll")                                                         \
    for (int mi = 0; mi < 4; mi++) {                                          \
        const uint32_t _ao = aoff + mi * (16 * BPITCH);                       \
        LDSM4(af[mi][0], af[mi][1], af[mi][2], af[mi][3], (A16B) + _ao);      \
    }                                                                         \
    _Pragma("unroll")                                                         \
    for (int nj = 0; nj < 4; nj++) {                                          \
        const int n = bn0 + nj * 8 + qr;                                      \
        const float x0 = (BP)[(2 * qc) * PAD + n];                            \
        const float x1 = (BP)[(2 * qc + 1) * PAD + n];                        \
        const float x2 = (BP)[(2 * qc + 8) * PAD + n];                        \
        const float x3 = (BP)[(2 * qc + 9) * PAD + n];                        \
        asm("cvt.rn.f16x2.f32 %0, %1, %2;" : "=r"(bfr[nj][0]) : "f"(x1), "f"(x0)); \
        asm("cvt.rn.f16x2.f32 %0, %1, %2;" : "=r"(bfr[nj][1]) : "f"(x3), "f"(x2)); \
    }                                                                         \
    _Pragma("unroll")                                                         \
    for (int mi = 0; mi < 4; mi++)                                            \
        _Pragma("unroll")                                                     \
        for (int nj = 0; nj < 4; nj++)                                        \
            mma16h(acc[mi][nj], af[mi], bfr[nj]);                             \
} while (0)

#define WARP_IDX_SETUP                                  \
    const int tid = threadIdx.x;                        \
    const int lane = tid & 31, wid = tid >> 5;          \
    const int qr = lane >> 2, qc = lane & 3;            \
    const int am0 = (wid >> 2) * 64;                    \
    const int bn0 = (wid & 3) * 32;                     \
    const int lrow = tid >> 2, lcol = (tid & 3) * 4;    \
    const int krow = tid >> 5, ncol = (tid & 31) * 4;   \
    (void)qr; (void)qc; (void)lrow; (void)lcol; (void)krow; (void)ncol; (void)wid;

#define LDSM_A_IDX                                                            \
    const int a_row = ((lane >> 3) & 1) * 8 + (lane & 7);                     \
    const int a_kh  = ((lane >> 4) & 1) * 16;
#define LDSM_B_IDX                                                            \
    const int b_row = ((lane >> 4) & 1) * 8 + (lane & 7);                     \
    const int b_kh  = ((lane >> 3) & 1) * 16;

// ---------------------------------------------------------------------------
// k_prep: per-batch mask compaction (prefix scan).
// ---------------------------------------------------------------------------
__global__ __launch_bounds__(256)
void k_prep(const int* __restrict__ mask)
{
    const int b = blockIdx.x;
    const int tid = threadIdx.x;
    const int lane = tid & 31, wid = tid >> 5;
    __shared__ int wtot[8];
    __shared__ int woff[8];
    __shared__ int s_total;

    const int f0 = mask[(size_t)b * SS + 2 * tid];
    const int f1 = mask[(size_t)b * SS + 2 * tid + 1];
    const int sum = f0 + f1;
    int x = sum;
#pragma unroll
    for (int o = 1; o < 32; o <<= 1) {
        int y = __shfl_up_sync(0xffffffffu, x, o);
        if (lane >= o) x += y;
    }
    if (lane == 31) wtot[wid] = x;
    __syncthreads();
    if (wid == 0) {
        int w = (lane < 8) ? wtot[lane] : 0;
        int xx = w;
#pragma unroll
        for (int o = 1; o < 8; o <<= 1) {
            int y = __shfl_up_sync(0xffffffffu, xx, o);
            if (lane >= o) xx += y;
        }
        if (lane < 8) woff[lane] = xx - w;
        if (lane == 7) s_total = xx;
    }
    __syncthreads();
    int off = woff[wid] + x - sum;
    if (f0) g_idx[(size_t)b * SS + off++] = 2 * tid;
    if (f1) g_idx[(size_t)b * SS + off] = 2 * tid + 1;
    const int total = s_total;
    if (tid == 0) g_cnt[b] = total;
    for (int j = total + tid; j < SS; j += 256) g_idx[(size_t)b * SS + j] = 0;
}

// Kernel c: c[m] = sum_d dec[m,d] * b_attn[d]
__global__ __launch_bounds__(256)
void k_c(const float* __restrict__ dec, const float* __restrict__ ba)
{
    const int m = blockIdx.x * 8 + (threadIdx.x >> 5);
    const int lane = threadIdx.x & 31;
    float s = 0.0f;
#pragma unroll
    for (int it = 0; it < 4; it++) {
        float4 v = *(const float4*)&dec[(size_t)m * DD + it * 128 + lane * 4];
        float4 w = *(const float4*)&ba[it * 128 + lane * 4];
        s += v.x * w.x + v.y * w.y + v.z * w.z + v.w * w.w;
    }
#pragma unroll
    for (int o = 16; o; o >>= 1) s += __shfl_xor_sync(0xffffffffu, s, o);
    if (lane == 0) g_c[m] = s;
}

// k_P (bf16-split + ldmatrix): P[m,e] = sum_d dec[m,d]*W[e,d]; stores P pre-split.
__global__ __launch_bounds__(256, 2)
void k_P(const float* __restrict__ dec, const float* __restrict__ W)
{
    extern __shared__ char smx[];
    WARP_IDX_SETUP
    LDSM_A_IDX
    LDSM_B_IDX
    const int bm = blockIdx.y * 128, bn = blockIdx.x * 128;
    const uint32_t sb = smem_u32(smx);
    const uint32_t aoff = (am0 + a_row) * BPITCH + a_kh;
    const uint32_t boff = (bn0 + b_row) * BPITCH + b_kh;

    float4 va[2], vb[2];
#pragma unroll
    for (int p = 0; p < 2; p++) {
        va[p] = *(const float4*)&dec[(size_t)(bm + lrow + p * 64) * DD + lcol];
        vb[p] = *(const float4*)&W[(size_t)(bn + lrow + p * 64) * DD + lcol];
    }
    {
        char* b0 = smx;
        STAGE_BF2(b0, b0 + BTILE, va[0], 0); STAGE_BF2(b0, b0 + BTILE, va[1], 1);
        STAGE_BF2(b0 + 2*BTILE, b0 + 3*BTILE, vb[0], 0);
        STAGE_BF2(b0 + 2*BTILE, b0 + 3*BTILE, vb[1], 1);
    }
    __syncthreads();

    float acc[4][4][4] = {};
    const int nt = DD / 16;
    for (int t = 0; t < nt; t++) {
        const int cur = t & 1, nxt = cur ^ 1;
        const bool more = (t + 1 < nt);
        if (more) {
            const int k0 = (t + 1) * 16;
#pragma unroll
            for (int p = 0; p < 2; p++) {
                va[p] = *(const float4*)&dec[(size_t)(bm + lrow + p * 64) * DD + k0 + lcol];
                vb[p] = *(const float4*)&W[(size_t)(bn + lrow + p * 64) * DD + k0 + lcol];
            }
        }
        {
            const uint32_t s0 = sb + cur * BSTG;
            COMPUTE_BF_LDSM(s0, s0 + BTILE, s0 + 2*BTILE, s0 + 3*BTILE);
        }
        if (more) {
            char* b1 = smx + nxt * BSTG;
            STAGE_BF2(b1, b1 + BTILE, va[0], 0); STAGE_BF2(b1, b1 + BTILE, va[1], 1);
            STAGE_BF2(b1 + 2*BTILE, b1 + 3*BTILE, vb[0], 0);
            STAGE_BF2(b1 + 2*BTILE, b1 + 3*BTILE, vb[1], 1);
        }
        __syncthreads();
    }
#pragma unroll
    for (int mi = 0; mi < 4; mi++)
#pragma unroll
        for (int nj = 0; nj < 4; nj++) {
            const size_t m = bm + am0 + mi * 16 + qr;
            const int n = bn + bn0 + nj * 8 + qc * 2;
            uint32_t h, l;
            split2(acc[mi][nj][0], acc[mi][nj][1], h, l);
            g_Ph[(m * EE + n) >> 1] = h; g_Pl[(m * EE + n) >> 1] = l;
            split2(acc[mi][nj][2], acc[mi][nj][3], h, l);
            g_Ph[((m + 8) * EE + n) >> 1] = h; g_Pl[((m + 8) * EE + n) >> 1] = l;
        }
}

// k_energy (N-compacted, split-K, pre-split A): partials into g_ep.
__global__ __launch_bounds__(256, 2)
void k_energy(const float* __restrict__ enc)
{
    extern __shared__ char smx[];
    WARP_IDX_SETUP
    LDSM_A_IDX
    LDSM_B_IDX
    const int b = blockIdx.z;
    const int kh = blockIdx.y;
    const int bn = blockIdx.x * 128;
    const int cnt_b = g_cnt[b];
    if (bn >= cnt_b) return;

    // pre-split P: pair arrays, row stride EE/2 u32
    const uint32_t* Aph = g_Ph + ((size_t)b * TT * EE + (size_t)kh * (EE / 2)) / 2;
    const uint32_t* Apl = g_Pl + ((size_t)b * TT * EE + (size_t)kh * (EE / 2)) / 2;
    const float* Ep = enc + (size_t)b * SS * EE + (size_t)kh * (EE / 2);
    const uint32_t sb = smem_u32(smx);
    const uint32_t aoff = (am0 + a_row) * BPITCH + a_kh;
    const uint32_t boff = (bn0 + b_row) * BPITCH + b_kh;
    const int pcol = (tid & 3) * 2;  // pair column within 16-k tile

    const int sidx0 = g_idx[(size_t)b * SS + bn + lrow];
    const int sidx1 = g_idx[(size_t)b * SS + bn + lrow + 64];

    uint2 hva[2], lva[2];
    float4 vb[2];
    hva[0] = *(const uint2*)&Aph[(size_t)lrow * (EE/2) + pcol];
    hva[1] = *(const uint2*)&Aph[(size_t)(lrow + 64) * (EE/2) + pcol];
    lva[0] = *(const uint2*)&Apl[(size_t)lrow * (EE/2) + pcol];
    lva[1] = *(const uint2*)&Apl[(size_t)(lrow + 64) * (EE/2) + pcol];
    vb[0] = *(const float4*)&Ep[(size_t)sidx0 * EE + lcol];
    vb[1] = *(const float4*)&Ep[(size_t)sidx1 * EE + lcol];
    {
        char* b0 = smx;
        STAGE_PRE(b0, b0 + BTILE, hva[0], lva[0], 0);
        STAGE_PRE(b0, b0 + BTILE, hva[1], lva[1], 1);
        STAGE_BF2(b0 + 2*BTILE, b0 + 3*BTILE, vb[0], 0);
        STAGE_BF2(b0 + 2*BTILE, b0 + 3*BTILE, vb[1], 1);
    }
    __syncthreads();

    float acc[4][4][4] = {};
    const int nt = (EE / 2) / 16;  // 32
    for (int t = 0; t < nt; t++) {
        const int cur = t & 1, nxt = cur ^ 1;
        const bool more = (t + 1 < nt);
        if (more) {
            const int k0 = (t + 1) * 16;
            const int pc = k0 / 2 + pcol;
            hva[0] = *(const uint2*)&Aph[(size_t)lrow * (EE/2) + pc];
            hva[1] = *(const uint2*)&Aph[(size_t)(lrow + 64) * (EE/2) + pc];
            lva[0] = *(const uint2*)&Apl[(size_t)lrow * (EE/2) + pc];
            lva[1] = *(const uint2*)&Apl[(size_t)(lrow + 64) * (EE/2) + pc];
            vb[0] = *(const float4*)&Ep[(size_t)sidx0 * EE + k0 + lcol];
            vb[1] = *(const float4*)&Ep[(size_t)sidx1 * EE + k0 + lcol];
        }
        {
            const uint32_t s0 = sb + cur * BSTG;
            COMPUTE_BF_LDSM(s0, s0 + BTILE, s0 + 2*BTILE, s0 + 3*BTILE);
        }
        if (more) {
            char* b1 = smx + nxt * BSTG;
            STAGE_PRE(b1, b1 + BTILE, hva[0], lva[0], 0);
            STAGE_PRE(b1, b1 + BTILE, hva[1], lva[1], 1);
            STAGE_BF2(b1 + 2*BTILE, b1 + 3*BTILE, vb[0], 0);
            STAGE_BF2(b1 + 2*BTILE, b1 + 3*BTILE, vb[1], 1);
        }
        __syncthreads();
    }
    float* ep = g_ep + (size_t)kh * BB * TT * SS + (size_t)b * TT * SS;
#pragma unroll
    for (int mi = 0; mi < 4; mi++) {
        const int t0 = am0 + mi * 16 + qr;
#pragma unroll
        for (int nj = 0; nj < 4; nj++) {
            const int j0 = bn + bn0 + nj * 8 + qc * 2;
            *(float2*)&ep[(size_t)t0 * SS + j0]       = make_float2(acc[mi][nj][0], acc[mi][nj][1]);
            *(float2*)&ep[(size_t)(t0 + 8) * SS + j0] = make_float2(acc[mi][nj][2], acc[mi][nj][3]);
        }
    }
}

// Fused combine + softmax; writes full me/attn rows via SMEM scatter (coalesced).
__global__ __launch_bounds__(256)
void k_softmax(float* __restrict__ me, float* __restrict__ attn)
{
    const int row = blockIdx.x;
    const int b = row >> 7;  // TT = 128
    const int tid = threadIdx.x;
    const int cnt_b = g_cnt[b];
    __shared__ float smax[8];
    __shared__ float ssum[8];
    __shared__ float s_me[SS];
    __shared__ float s_at[SS];

    float* mrow = me + (size_t)row * SS;
    float* yrow = attn + (size_t)row * SS;

    s_me[tid] = NEGINF; s_me[tid + 256] = NEGINF;
    s_at[tid] = 0.0f;   s_at[tid + 256] = 0.0f;

    if (cnt_b == 0) {
        const float u = 1.0f / SS;
        mrow[tid] = NEGINF; mrow[tid + 256] = NEGINF;
        yrow[tid] = u; yrow[tid + 256] = u;
        g_attn_c[(size_t)row * SS + tid] = 0.0f;
        g_attn_c[(size_t)row * SS + tid + 256] = 0.0f;
        return;
    }

    const float ct = g_c[row];
    const float* p0 = g_ep + (size_t)row * SS;
    const float* p1 = g_ep + (size_t)BB * TT * SS + (size_t)row * SS;
    const int j0 = tid, j1 = tid + 256;
    const float e0 = (j0 < cnt_b) ? p0[j0] + p1[j0] + ct : -FLT_MAX;
    const float e1 = (j1 < cnt_b) ? p0[j1] + p1[j1] + ct : -FLT_MAX;

    float m = fmaxf(e0, e1);
#pragma unroll
    for (int o = 16; o; o >>= 1) m = fmaxf(m, __shfl_xor_sync(0xffffffffu, m, o));
    if ((tid & 31) == 0) smax[tid >> 5] = m;
    __syncthreads();
    float M = smax[0];
#pragma unroll
    for (int i = 1; i < 8; i++) M = fmaxf(M, smax[i]);

    const float x0 = (j0 < cnt_b) ? __expf(e0 - M) : 0.0f;
    const float x1 = (j1 < cnt_b) ? __expf(e1 - M) : 0.0f;
    float s = x0 + x1;
#pragma unroll
    for (int o = 16; o; o >>= 1) s += __shfl_xor_sync(0xffffffffu, s, o);
    if ((tid & 31) == 0) ssum[tid >> 5] = s;
    __syncthreads();
    float S = 0.0f;
#pragma unroll
    for (int i = 0; i < 8; i++) S += ssum[i];
    const float inv = 1.0f / S;
    const float a0 = x0 * inv, a1 = x1 * inv;

    g_attn_c[(size_t)row * SS + j0] = a0;
    g_attn_c[(size_t)row * SS + j1] = a1;

    // scatter in SMEM, then coalesced row stores
    if (j0 < cnt_b) {
        const int s0 = g_idx[(size_t)b * SS + j0];
        s_me[s0] = e0; s_at[s0] = a0;
    }
    if (j1 < cnt_b) {
        const int s1 = g_idx[(size_t)b * SS + j1];
        s_me[s1] = e1; s_at[s1] = a1;
    }
    __syncthreads();
    mrow[tid] = s_me[tid]; mrow[tid + 256] = s_me[tid + 256];
    yrow[tid] = s_at[tid]; yrow[tid + 256] = s_at[tid + 256];
}

// k_wc (fp16 k16, k-compacted, per batch)
__global__ __launch_bounds__(256, 2)
void k_wc(const float* __restrict__ enc)
{
    __shared__ char A16[2][BTILE];
    __shared__ float Bf[2][16][PAD];
    WARP_IDX_SETUP
    LDSM_A_IDX
    const int b = blockIdx.z;
    const int bn = blockIdx.x * 128;
    const int cnt_b = g_cnt[b];
    const int nk = (cnt_b + 15) >> 4;
    const float* A = g_attn_c + (size_t)b * TT * SS;
    const float* Ep = enc + (size_t)b * SS * EE;
    const int* ib = g_idx + (size_t)b * SS;
    const uint32_t a16b[2] = { smem_u32(A16[0]), smem_u32(A16[1]) };
    const uint32_t aoff = (am0 + a_row) * BPITCH + a_kh;

    float4 va[2], vb[2];
#pragma unroll
    for (int p = 0; p < 2; p++) {
        va[p] = *(const float4*)&A[(size_t)(lrow + p * 64) * SS + lcol];
        vb[p] = *(const float4*)&Ep[(size_t)ib[krow + p * 8] * EE + bn + ncol];
    }
    STAGE_F16(A16[0], va[0], 0); STAGE_F16(A16[0], va[1], 1);
    STAGE_RAW(Bf[0], vb[0], 0); STAGE_RAW(Bf[0], vb[1], 1);
    __syncthreads();

    float acc[4][4][4] = {};
    for (int t = 0; t < nk; t++) {
        const int cur = t & 1, nxt = cur ^ 1;
        const bool more = (t + 1 < nk);
        if (more) {
            const int k0 = (t + 1) * 16;
#pragma unroll
            for (int p = 0; p < 2; p++) {
                va[p] = *(const float4*)&A[(size_t)(lrow + p * 64) * SS + k0 + lcol];
                vb[p] = *(const float4*)&Ep[(size_t)ib[k0 + krow + p * 8] * EE + bn + ncol];
            }
        }
        COMPUTE_F16(a16b[cur], &Bf[cur][0][0]);
        if (more) {
            STAGE_F16(A16[nxt], va[0], 0); STAGE_F16(A16[nxt], va[1], 1);
            STAGE_RAW(Bf[nxt], vb[0], 0); STAGE_RAW(Bf[nxt], vb[1], 1);
        }
        __syncthreads();
    }
#pragma unroll
    for (int mi = 0; mi < 4; mi++)
#pragma unroll
        for (int nj = 0; nj < 4; nj++) {
            const size_t m = (size_t)b * TT + am0 + mi * 16 + qr;
            const int n = bn + bn0 + nj * 8 + qc * 2;
            *(float2*)&g_wc[m * EE + n]       = make_float2(acc[mi][nj][0], acc[mi][nj][1]);
            *(float2*)&g_wc[(m + 8) * EE + n] = make_float2(acc[mi][nj][2], acc[mi][nj][3]);
        }
}

// k_out (fp16 k16, split-K=2): partials (no tanh) into g_ep.
__global__ __launch_bounds__(256, 2)
void k_out(const float* __restrict__ dec, const float* __restrict__ Wout)
{
    __shared__ char A16[2][BTILE];
    __shared__ float Bf[2][16][PAD];
    WARP_IDX_SETUP
    LDSM_A_IDX
    const int bm = blockIdx.y * 128, bn = blockIdx.x * 128;
    const int kh = blockIdx.z;
    const int kb = kh * ((EE + DD) / 2);   // 0 or 768
    const uint32_t a16b[2] = { smem_u32(A16[0]), smem_u32(A16[1]) };
    const uint32_t aoff = (am0 + a_row) * BPITCH + a_kh;

    float4 va[2], vb[2];
#pragma unroll
    for (int p = 0; p < 2; p++) {
        if (kb < EE)
            va[p] = *(const float4*)&g_wc[(size_t)(bm + lrow + p * 64) * EE + kb + lcol];
        else
            va[p] = *(const float4*)&dec[(size_t)(bm + lrow + p * 64) * DD + (kb - EE) + lcol];
        vb[p] = *(const float4*)&Wout[(size_t)(kb + krow + p * 8) * DD + bn + ncol];
    }
    STAGE_F16(A16[0], va[0], 0); STAGE_F16(A16[0], va[1], 1);
    STAGE_RAW(Bf[0], vb[0], 0); STAGE_RAW(Bf[0], vb[1], 1);
    __syncthreads();

    float acc[4][4][4] = {};
    const int nt = (EE + DD) / 32;   // 48 tiles per half
    for (int t = 0; t < nt; t++) {
        const int cur = t & 1, nxt = cur ^ 1;
        const bool more = (t + 1 < nt);
        if (more) {
            const int k0 = kb + (t + 1) * 16;
#pragma unroll
            for (int p = 0; p < 2; p++) {
                if (k0 < EE)
                    va[p] = *(const float4*)&g_wc[(size_t)(bm + lrow + p * 64) * EE + k0 + lcol];
                else
                    va[p] = *(const float4*)&dec[(size_t)(bm + lrow + p * 64) * DD + (k0 - EE) + lcol];
                vb[p] = *(const float4*)&Wout[(size_t)(k0 + krow + p * 8) * DD + bn + ncol];
            }
        }
        COMPUTE_F16(a16b[cur], &Bf[cur][0][0]);
        if (more) {
            STAGE_F16(A16[nxt], va[0], 0); STAGE_F16(A16[nxt], va[1], 1);
            STAGE_RAW(Bf[nxt], vb[0], 0); STAGE_RAW(Bf[nxt], vb[1], 1);
        }
        __syncthreads();
    }
    float* part = g_ep + (size_t)kh * BB * TT * DD;
#pragma unroll
    for (int mi = 0; mi < 4; mi++)
#pragma unroll
        for (int nj = 0; nj < 4; nj++) {
            const size_t m = bm + am0 + mi * 16 + qr;
            const int n = bn + bn0 + nj * 8 + qc * 2;
            *(float2*)&part[m * DD + n]       = make_float2(acc[mi][nj][0], acc[mi][nj][1]);
            *(float2*)&part[(m + 8) * DD + n] = make_float2(acc[mi][nj][2], acc[mi][nj][3]);
        }
}

// k_outc: ht = tanh(p0 + p1)
__global__ __launch_bounds__(256)
void k_outc(float* __restrict__ ht)
{
    const size_t i = (size_t)blockIdx.x * 256 + threadIdx.x;
    const size_t n4 = (size_t)BB * TT * DD / 4;
    if (i >= n4) return;
    const float4 a = ((const float4*)g_ep)[i];
    const float4 b = ((const float4*)(g_ep + (size_t)BB * TT * DD))[i];
    float4 r;
    r.x = tanhf(a.x + b.x); r.y = tanhf(a.y + b.y);
    r.z = tanhf(a.z + b.z); r.w = tanhf(a.w + b.w);
    ((float4*)ht)[i] = r;
}

extern "C" void kernel_launch(void* const* d_in, const int* in_sizes, int n_in,
                              void* d_out, int out_size)
{
    const float* dec    = (const float*)d_in[0];
    const float* enc    = (const float*)d_in[1];
    const int*   mask   = (const int*)d_in[2];
    const float* W_attn = (const float*)d_in[3];
    const float* b_attn = (const float*)d_in[4];
    const float* W_out  = (const float*)d_in[5];
    float* out = (float*)d_out;

    const size_t n_h    = (size_t)BB * TT * DD;
    const size_t n_attn = (size_t)BB * TT * SS;
    const size_t n_me   = (size_t)BB * TT * SS;

    float* h_tilde = out;
    float* attn;
    float* me;
    if ((size_t)out_size >= n_h + n_attn + n_me) {
        attn = out + n_h;
        me   = out + n_h + n_attn;
    } else {
        void* p;
        cudaGetSymbolAddress(&p, g_attn_scratch); attn = (float*)p;
        cudaGetSymbolAddress(&p, g_me_scratch);   me = (float*)p;
    }

    cudaFuncSetAttribute(k_P, cudaFuncAttributeMaxDynamicSharedMemorySize, SMEM_BF);
    cudaFuncSetAttribute(k_energy, cudaFuncAttributeMaxDynamicSharedMemorySize, SMEM_BF);

    // 0. mask compaction ;  c = dec . b_attn
    k_prep<<<dim3(BB), 256>>>(mask);
    k_c<<<dim3(BB * TT / 8), 256>>>(dec, b_attn);
    // 1. P = dec @ W_attn^T (bf16-split; stored pre-split)  M=8192 N=1024 K=512
    k_P<<<dim3(EE / 128, (BB * TT) / 128), 256, SMEM_BF>>>(dec, W_attn);
    // 2. energy partials, N-compacted + split-K=2
    k_energy<<<dim3(SS / 128, 2, BB), 256, SMEM_BF>>>(enc);
    // 3. fused combine + softmax (coalesced me/attn rows, compacted attn_c)
    k_softmax<<<dim3(BB * TT), 256>>>(me, attn);
    // 4. weighted context, k-compacted (fp16 k16)
    k_wc<<<dim3(EE / 128, 1, BB), 256>>>(enc);
    // 5. out partials (fp16 k16, split-K=2), then combine + tanh
    k_out<<<dim3(DD / 128, (BB * TT) / 128, 2), 256>>>(dec, W_out);
    k_outc<<<dim3((BB * TT * DD / 4 + 255) / 256), 256>>>(h_tilde);
}